// round 9
// baseline (speedup 1.0000x reference)
#include <cuda_runtime.h>
#include <cuda_bf16.h>

// <Z_0> after RY·RX on all qubits + CNOT chain reduces analytically to the
// qubit-0 gate only (CNOTs preserve the q0 bit; gates on q1..q15 are
// block-unitary and preserve per-block norms):
//   A = ||u||^2 - ||v||^2,  S = sum(u * conj(v))   (u = top half, v = bottom)
//   <Z_0> = cos^2(t) * A - 2 sin(t) * (Re S + cos(t) * Im S)
//
// R8: the one untested cell in the design matrix: all 148 SMs active AND
// 64-reg budget AND static pipelined guard-free loop. R6 tested this
// structure but omitted the ",1" in __launch_bounds__, so ptxas budgeted for
// 2 CTAs/SM (regs=34) and serialized the loads. Here: grid (128, 2) x 1024
// threads, __launch_bounds__(1024, 1), R7's winning inner loop (distance-1
// software pipeline + split accumulators), 64KB per-block streams, two-slot
// deterministic per-row combine with counter reset for graph replay.

#ifndef QN
#define QN 16
#endif
static constexpr int D     = 1 << QN;     // 65536
static constexpr int HALF  = D >> 1;      // 32768 floats per half-row
static constexpr int HALF4 = HALF >> 2;   // 8192 float4 per half-row
static constexpr int SPLIT = 2;
static constexpr int NT    = 1024;
static constexpr int CHUNK4 = HALF4 / SPLIT;   // 4096 float4 per block
static constexpr int ITERS  = CHUNK4 / NT;     // 4 (compile-time, exact)
static constexpr int MAXB   = 512;

__device__ float    g_part[MAXB * SPLIT * 3];
__device__ unsigned g_cnt[MAXB];          // zero at load; reset each launch

__inline__ __device__ float warp_sum(float v) {
    #pragma unroll
    for (int o = 16; o > 0; o >>= 1)
        v += __shfl_down_sync(0xffffffffu, v, o);
    return v;
}

__global__ __launch_bounds__(NT, 1)      // ",1" is load-bearing: 64-reg budget
void zexp_kernel(const float* __restrict__ re,
                 const float* __restrict__ im,
                 const float* __restrict__ thetas,
                 float* __restrict__ out)
{
    const int row = blockIdx.x;
    const int sp  = blockIdx.y;
    const size_t base = (size_t)row * D;
    const int coff = sp * CHUNK4;

    const float4* __restrict__ ru = (const float4*)(re + base)        + coff;
    const float4* __restrict__ rv = (const float4*)(re + base + HALF) + coff;
    const float4* __restrict__ iu = (const float4*)(im + base)        + coff;
    const float4* __restrict__ iv = (const float4*)(im + base + HALF) + coff;

    const int t = threadIdx.x;

    // prologue: iteration 0 loads (4 LDG.128 in flight + 4 more pipelined)
    float4 a = ru[t], b = rv[t], c = iu[t], d = iv[t];

    float A0 = 0.f, A1 = 0.f, P0 = 0.f, P1 = 0.f, Q0 = 0.f, Q1 = 0.f;

    #pragma unroll
    for (int k = 0; k < ITERS; ++k) {
        float4 na, nb, nc, nd;
        if (k + 1 < ITERS) {                 // compile-time guard (unrolled)
            const int idx = t + (k + 1) * NT;
            na = ru[idx]; nb = rv[idx]; nc = iu[idx]; nd = iv[idx];
        }

        // split accumulators: x,y -> set0, z,w -> set1 (half-length chains)
        A0 += (a.x*a.x + c.x*c.x) - (b.x*b.x + d.x*d.x);
        A0 += (a.y*a.y + c.y*c.y) - (b.y*b.y + d.y*d.y);
        A1 += (a.z*a.z + c.z*c.z) - (b.z*b.z + d.z*d.z);
        A1 += (a.w*a.w + c.w*c.w) - (b.w*b.w + d.w*d.w);

        P0 += a.x*b.x + c.x*d.x;
        P0 += a.y*b.y + c.y*d.y;
        P1 += a.z*b.z + c.z*d.z;
        P1 += a.w*b.w + c.w*d.w;

        Q0 += c.x*b.x - a.x*d.x;
        Q0 += c.y*b.y - a.y*d.y;
        Q1 += c.z*b.z - a.z*d.z;
        Q1 += c.w*b.w - a.w*d.w;

        if (k + 1 < ITERS) { a = na; b = nb; c = nc; d = nd; }
    }

    float A = A0 + A1, P = P0 + P1, Q = Q0 + Q1;

    A = warp_sum(A);
    P = warp_sum(P);
    Q = warp_sum(Q);

    __shared__ float sA[NT / 32], sP[NT / 32], sQ[NT / 32];
    const int lane = threadIdx.x & 31;
    const int wid  = threadIdx.x >> 5;
    if (lane == 0) { sA[wid] = A; sP[wid] = P; sQ[wid] = Q; }
    __syncthreads();

    if (threadIdx.x == 0) {
        float tA = 0.f, tP = 0.f, tQ = 0.f;
        #pragma unroll
        for (int w = 0; w < NT / 32; ++w) { tA += sA[w]; tP += sP[w]; tQ += sQ[w]; }

        float* slot = &g_part[(row * SPLIT + sp) * 3];
        slot[0] = tA; slot[1] = tP; slot[2] = tQ;
        __threadfence();

        const unsigned old = atomicAdd(&g_cnt[row], 1u);
        if (old == SPLIT - 1) {
            __threadfence();
            const float* p = &g_part[row * SPLIT * 3];
            float fA = 0.f, fP = 0.f, fQ = 0.f;
            #pragma unroll
            for (int s = 0; s < SPLIT; ++s) {   // fixed order: deterministic
                fA += p[s * 3 + 0];
                fP += p[s * 3 + 1];
                fQ += p[s * 3 + 2];
            }
            const float t0 = thetas[0];
            const float ct = cosf(t0);
            const float st = sinf(t0);
            out[row] = ct * ct * fA - 2.f * st * (fP + ct * fQ);
            atomicExch(&g_cnt[row], 0u);        // clean for next graph replay
        }
    }
}

extern "C" void kernel_launch(void* const* d_in, const int* in_sizes, int n_in,
                              void* d_out, int out_size)
{
    const float* re     = (const float*)d_in[0];  // states_re (B, 65536)
    const float* im     = (const float*)d_in[1];  // states_im (B, 65536)
    const float* thetas = (const float*)d_in[2];  // (16,)
    float* out = (float*)d_out;                   // (B,)

    const int B = in_sizes[0] / D;                // 128
    dim3 grid(B, SPLIT);
    zexp_kernel<<<grid, NT>>>(re, im, thetas, out);
}

// round 10
// speedup vs baseline: 1.2116x; 1.2116x over previous
#include <cuda_runtime.h>
#include <cuda_bf16.h>

// <Z_0> after RY·RX on all qubits + CNOT chain reduces analytically to the
// qubit-0 gate only (CNOTs preserve the q0 bit; gates on q1..q15 are
// block-unitary and preserve per-block norms):
//   A = ||u||^2 - ||v||^2,  S = sum(u * conj(v))   (u = top half, v = bottom)
//   <Z_0> = cos^2(t) * A - 2 sin(t) * (Re S + cos(t) * Im S)
//
// R9: grid=128 x 1024 (one balanced wave -- R8 proved grid>148 runs 2 waves
// at 1 CTA/SM and always loses) with the pipeline deepened to distance-2:
// 16 LDG.128 in flight per thread (vs 8 in R7), hiding residual DRAM-latency
// bubbles at iteration boundaries. Register economy: 2 staging buffers
// (32 regs) + 3 accumulators + UR-promoted block-uniform bases stays under
// the 64-reg budget of __launch_bounds__(1024,1).

#ifndef QN
#define QN 16
#endif
static constexpr int D     = 1 << QN;     // 65536
static constexpr int HALF  = D >> 1;      // 32768 floats per half-row
static constexpr int HALF4 = HALF >> 2;   // 8192 float4 per half-row
static constexpr int NTHREADS = 1024;
static constexpr int ITERS = HALF4 / NTHREADS;  // 8 (compile-time, exact)

__inline__ __device__ float warp_sum(float v) {
    #pragma unroll
    for (int o = 16; o > 0; o >>= 1)
        v += __shfl_down_sync(0xffffffffu, v, o);
    return v;
}

__global__ __launch_bounds__(NTHREADS, 1)
void zexp_kernel(const float* __restrict__ re,
                 const float* __restrict__ im,
                 const float* __restrict__ thetas,
                 float* __restrict__ out)
{
    const int row = blockIdx.x;
    const size_t base = (size_t)row * D;

    const float4* __restrict__ ru = (const float4*)(re + base);          // u_r
    const float4* __restrict__ rv = (const float4*)(re + base + HALF);   // v_r
    const float4* __restrict__ iu = (const float4*)(im + base);          // u_i
    const float4* __restrict__ iv = (const float4*)(im + base + HALF);   // v_i

    const int t = threadIdx.x;

    // distance-2 software pipeline: two staging buffers, 16 LDG.128 in flight
    float4 a0 = ru[t],            b0 = rv[t],            c0 = iu[t],            d0 = iv[t];
    float4 a1 = ru[t + NTHREADS], b1 = rv[t + NTHREADS], c1 = iu[t + NTHREADS], d1 = iv[t + NTHREADS];

    float A = 0.f, P = 0.f, Q = 0.f;

    #pragma unroll
    for (int k = 0; k < ITERS; ++k) {
        // consume the even/odd buffer for iteration k (compile-time select)
        const float4 a = (k & 1) ? a1 : a0;
        const float4 b = (k & 1) ? b1 : b0;
        const float4 c = (k & 1) ? c1 : c0;
        const float4 d = (k & 1) ? d1 : d0;

        // refill the just-consumed buffer with iteration k+2 (if it exists)
        if (k + 2 < ITERS) {
            const int idx = t + (k + 2) * NTHREADS;
            if (k & 1) { a1 = ru[idx]; b1 = rv[idx]; c1 = iu[idx]; d1 = iv[idx]; }
            else       { a0 = ru[idx]; b0 = rv[idx]; c0 = iu[idx]; d0 = iv[idx]; }
        }

        A += (a.x*a.x + c.x*c.x) - (b.x*b.x + d.x*d.x);
        A += (a.y*a.y + c.y*c.y) - (b.y*b.y + d.y*d.y);
        A += (a.z*a.z + c.z*c.z) - (b.z*b.z + d.z*d.z);
        A += (a.w*a.w + c.w*c.w) - (b.w*b.w + d.w*d.w);

        P += a.x*b.x + c.x*d.x;
        P += a.y*b.y + c.y*d.y;
        P += a.z*b.z + c.z*d.z;
        P += a.w*b.w + c.w*d.w;

        Q += c.x*b.x - a.x*d.x;
        Q += c.y*b.y - a.y*d.y;
        Q += c.z*b.z - a.z*d.z;
        Q += c.w*b.w - a.w*d.w;
    }

    A = warp_sum(A);
    P = warp_sum(P);
    Q = warp_sum(Q);

    __shared__ float sA[NTHREADS / 32];
    __shared__ float sP[NTHREADS / 32];
    __shared__ float sQ[NTHREADS / 32];

    const int lane = threadIdx.x & 31;
    const int wid  = threadIdx.x >> 5;
    if (lane == 0) { sA[wid] = A; sP[wid] = P; sQ[wid] = Q; }
    __syncthreads();

    if (wid == 0) {
        A = (lane < NTHREADS / 32) ? sA[lane] : 0.f;
        P = (lane < NTHREADS / 32) ? sP[lane] : 0.f;
        Q = (lane < NTHREADS / 32) ? sQ[lane] : 0.f;
        A = warp_sum(A);
        P = warp_sum(P);
        Q = warp_sum(Q);
        if (lane == 0) {
            const float t0 = thetas[0];
            const float ct = cosf(t0);
            const float st = sinf(t0);
            out[row] = ct * ct * A - 2.f * st * (P + ct * Q);
        }
    }
}

extern "C" void kernel_launch(void* const* d_in, const int* in_sizes, int n_in,
                              void* d_out, int out_size)
{
    const float* re     = (const float*)d_in[0];  // states_re (B, 65536)
    const float* im     = (const float*)d_in[1];  // states_im (B, 65536)
    const float* thetas = (const float*)d_in[2];  // (16,)
    float* out = (float*)d_out;                   // (B,)

    const int B = in_sizes[0] / D;                // 128
    zexp_kernel<<<B, NTHREADS>>>(re, im, thetas, out);
}